// round 13
// baseline (speedup 1.0000x reference)
#include <cuda_runtime.h>
#include <cuda_fp16.h>
#include <math.h>
#include <stdint.h>

// ---------------- problem constants ----------------
#define Nn 262144
#define Dd 64
#define Kk 64
#define TPB 256
#define GRID 296                 // persistent CTAs (2/SM x 148)
#define NCH (Nn/32)              // 8192 m32 chunks
#define LOG2PI_F 1.83787706640934548356f
#define EXP2_F 7.389056098930650f     // exp(2) = exp(-prior_logvar_0)
#define LOG2E_F 1.44269504088896340736f

// ---------------- smem layout (bytes, dynamic) ----------------
// warp-private X/lp buffer: 32 rows * 72 halves * 2B = 4608B (also holds
// 16*68 floats = 4352B of lp staging in the epilogue)
#define WBUF 4608
#define OFF_B     0               // 8*4*32 float4 = 16384
#define OFF_STG   16384           // 8 * WBUF = 36864
#define OFF_OFFS  53248           // 64 f32
#define OFF_LPI   53504
#define OFF_WBG   53760
#define OFF_PHI   54016
#define OFF_SCR   54272           // 256 f32
#define SMEM_BYTES 55296

// ---------------- device globals ----------------
__device__ double g_lse;
__device__ unsigned int g_count;
__device__ unsigned int g_tile;

__device__ __forceinline__ void mma16(float c[4], const uint32_t a[4],
                                      uint32_t b0, uint32_t b1) {
    asm volatile("mma.sync.aligned.m16n8k16.row.col.f32.f16.f16.f32 "
        "{%0,%1,%2,%3},{%4,%5,%6,%7},{%8,%9},{%0,%1,%2,%3};"
        : "+f"(c[0]), "+f"(c[1]), "+f"(c[2]), "+f"(c[3])
        : "r"(a[0]), "r"(a[1]), "r"(a[2]), "r"(a[3]), "r"(b0), "r"(b1));
}
#define LDM_X4(A, addr) \
    asm volatile("ldmatrix.sync.aligned.m8n8.x4.shared.b16 {%0,%1,%2,%3}, [%4];" \
        : "=r"((A)[0]), "=r"((A)[1]), "=r"((A)[2]), "=r"((A)[3]) : "r"(addr))

__device__ __forceinline__ uint32_t h2sq(uint32_t a) {
    __half2 h = *reinterpret_cast<__half2*>(&a);
    __half2 q = __hmul2(h, h);
    return *reinterpret_cast<uint32_t*>(&q);
}
__device__ __forceinline__ uint32_t f2h2(float lo, float hi) {
    __half2 h = __floats2half2_rn(lo, hi);
    return *reinterpret_cast<uint32_t*>(&h);
}
__device__ __forceinline__ __half2 ex2_h2(float z0, float z1) {
    __half2 z = __floats2half2_rn(z0, z1);
    uint32_t zi = *reinterpret_cast<uint32_t*>(&z), r;
    asm("ex2.approx.f16x2 %0, %1;" : "=r"(r) : "r"(zi));
    return *reinterpret_cast<__half2*>(&r);
}

// ---------------------------------------------------------------------------
__global__ void __launch_bounds__(TPB, 2)
gmm_kernel(const float* __restrict__ X,
           const float* __restrict__ u_noise,
           const float* __restrict__ phi_logits,
           const float* __restrict__ q_mu,
           const float* __restrict__ q_logvar,
           const float* __restrict__ pi_logits,
           const float* __restrict__ prior_p,
           float* __restrict__ out)
{
    extern __shared__ char smraw[];
    float4* B_s    = (float4*)(smraw + OFF_B);
    float*  offs_s = (float*) (smraw + OFF_OFFS);
    float*  lpi_s  = (float*) (smraw + OFF_LPI);
    float*  wbg_s  = (float*) (smraw + OFF_WBG);
    float*  phi_s  = (float*) (smraw + OFF_PHI);
    float*  scr    = (float*) (smraw + OFF_SCR);

    __shared__ float bgp[8][32];           // per-warp per-row exact bg
    __shared__ float kl_s, c0_s;
    __shared__ double wsum[TPB / 32];

    const int tid = threadIdx.x, wid = tid >> 5, lane = tid & 31;
    const int g = lane >> 2, t4 = lane & 3;
    __half* bufh = (__half*)(smraw + OFF_STG + wid * WBUF);   // warp-private
    float*  buff = (float*) (smraw + OFF_STG + wid * WBUF);   // epilogue alias

    // ---------------- in-CTA precompute ----------------
    if (tid < 64) {
        float uu  = u_noise[tid];
        float gmb = -__logf(-__logf(uu + 1e-9f) + 1e-9f);
        float pl  = phi_logits[tid];
        float phi = 1.0f / (1.0f + __expf(-(pl + gmb)));
        phi_s[tid] = phi;
        float qphi = 1.0f / (1.0f + __expf(-pl));
        qphi = fminf(fmaxf(qphi, 1e-6f), 1.0f - 1e-6f);
        if (blockIdx.x == 0) out[1 + tid] = qphi;
        float p = fminf(fmaxf(prior_p[tid], 1e-6f), 1.0f - 1e-6f);
        scr[tid]       = qphi * (__logf(qphi) - __logf(p))
                       + (1.0f - qphi) * (__logf(1.0f - qphi) - __logf(1.0f - p));
        scr[64 + tid]  = (1.0f - phi) * (LOG2PI_F - 2.0f);
        scr[128 + tid] = pi_logits[tid];
        wbg_s[tid]     = (1.0f - phi) * EXP2_F;
    }
    __syncthreads();
    if (tid == 0) {
        float kl = 0.f, c0 = 0.f;
        #pragma unroll
        for (int i = 0; i < 64; i++) { kl += scr[i]; c0 += scr[64 + i]; }
        kl_s = kl; c0_s = c0;
    }
    if (tid < 64) {     // log(softmax(pi)+1e-9)
        float m = -3.4e38f;
        #pragma unroll
        for (int k = 0; k < 64; k++) m = fmaxf(m, scr[128 + k]);
        float ss = 0.f;
        #pragma unroll
        for (int k = 0; k < 64; k++) ss += __expf(scr[128 + k] - m);
        lpi_s[tid] = __logf(__expf(scr[128 + tid] - m) / ss + 1e-9f);
    }

    // packed B fragments: entry e = (j*4 + ks)*32 + le
    for (int e = tid; e < 8 * 4 * 32; e += TPB) {
        int le = e & 31, ks = (e >> 5) & 3, j = e >> 7;
        int n = 8 * j + (le >> 2);
        int d0 = 16 * ks + 2 * (le & 3);
        float lin[4], aa[4];
        #pragma unroll
        for (int p = 0; p < 4; p++) {
            int d = d0 + (p & 1) + (p >> 1) * 8;        // d0, d0+1, d0+8, d0+9
            float lv = fminf(fmaxf(q_logvar[n * Dd + d], -5.0f), 5.0f);
            float a  = phi_s[d] * __expf(-lv);
            aa[p]  = a;
            lin[p] = -2.0f * q_mu[n * Dd + d] * a;
        }
        float4 v;
        *(uint32_t*)&v.x = f2h2(lin[0], lin[1]);
        *(uint32_t*)&v.y = f2h2(lin[2], lin[3]);
        *(uint32_t*)&v.z = f2h2(aa[0],  aa[1]);
        *(uint32_t*)&v.w = f2h2(aa[2],  aa[3]);
        B_s[e] = v;
    }
    __syncthreads();    // scr free; reuse for offs partials
    {
        int k = tid & 63, part = tid >> 6;
        float s = 0.f;
        #pragma unroll
        for (int d = part * 16; d < part * 16 + 16; d++) {
            float lv = fminf(fmaxf(q_logvar[k * Dd + d], -5.0f), 5.0f);
            float a  = phi_s[d] * __expf(-lv);
            float mu = q_mu[k * Dd + d];
            s += phi_s[d] * (LOG2PI_F + lv) + mu * mu * a;
        }
        scr[tid] = s;
    }
    __syncthreads();
    if (tid < 64)
        offs_s[tid] = -0.5f * (scr[tid] + scr[64 + tid] + scr[128 + tid] + scr[192 + tid]);
    __syncthreads();    // LAST block sync; shared tables read-only below

    const float C0 = c0_s;
    double lsesum = 0.0;

    // ldmatrix per-lane base addresses (x4: lanes 0-15 rows, 16-31 k+8)
    uint32_t bsh = (uint32_t)__cvta_generic_to_shared(bufh);
    uint32_t lmb0 = bsh + (((uint32_t)(lane & 15)) * 72u + ((lane >> 4) << 3)) * 2u;
    uint32_t lmb1 = lmb0 + 16u * 72u * 2u;

    // =================== work-stealing per-warp m32 chunk loop ===================
    for (;;) {
        unsigned int tile;
        if (lane == 0) tile = atomicAdd(&g_tile, 1u);
        tile = __shfl_sync(0xffffffffu, tile, 0);
        if (tile >= NCH) break;
        const int row0 = (int)tile * 32;
        const float4* Xq = (const float4*)(X + (size_t)row0 * Dd);

        // ---- coalesced staging: LDG.128 -> fp16 smem + exact fp32 bg ----
        #pragma unroll
        for (int it = 0; it < 16; it++) {
            int i = lane + 32 * it;              // 512 float4s
            int row = i >> 4, q4 = (i & 15) << 2;
            float4 v = Xq[i];
            *(uint2*)(bufh + row * 72 + q4) =
                make_uint2(f2h2(v.x, v.y), f2h2(v.z, v.w));
            float4 w = *(const float4*)(wbg_s + q4);
            float s = fmaf(w.x, v.x*v.x, fmaf(w.y, v.y*v.y,
                      fmaf(w.z, v.z*v.z, w.w*v.w*v.w)));
            s += __shfl_xor_sync(0xffffffffu, s, 1);
            s += __shfl_xor_sync(0xffffffffu, s, 2);
            s += __shfl_xor_sync(0xffffffffu, s, 4);
            s += __shfl_xor_sync(0xffffffffu, s, 8);
            if ((lane & 15) == 0) bgp[wid][row] = s;
        }
        __syncwarp();

        // ---- MMA: ldmatrix A frags, in-register squares, 2 m16 tiles ----
        float c[2][8][4];
        #pragma unroll
        for (int u = 0; u < 2; u++)
            #pragma unroll
            for (int j = 0; j < 8; j++)
                { c[u][j][0]=0.f; c[u][j][1]=0.f; c[u][j][2]=0.f; c[u][j][3]=0.f; }

        #pragma unroll
        for (int ks = 0; ks < 4; ks++) {
            uint32_t A0[4], A1[4], Q0[4], Q1[4];
            LDM_X4(A0, lmb0 + ks * 32u);
            LDM_X4(A1, lmb1 + ks * 32u);
            #pragma unroll
            for (int p = 0; p < 4; p++) { Q0[p] = h2sq(A0[p]); Q1[p] = h2sq(A1[p]); }
            const float4* bp = B_s + ks * 32 + lane;
            #pragma unroll
            for (int j = 0; j < 8; j++) {
                float4 b = bp[j * 128];
                uint32_t bl0 = *(uint32_t*)&b.x, bl1 = *(uint32_t*)&b.y;
                uint32_t bq0 = *(uint32_t*)&b.z, bq1 = *(uint32_t*)&b.w;
                mma16(c[0][j], A0, bl0, bl1);
                mma16(c[0][j], Q0, bq0, bq1);
                mma16(c[1][j], A1, bl0, bl1);
                mma16(c[1][j], Q1, bq0, bq1);
            }
        }
        __syncwarp();        // A tile consumed; buffer reusable for lp staging

        // ---- epilogue per m16 tile: lse + stage + coalesced copy-out ----
        #pragma unroll
        for (int u = 0; u < 2; u++) {
            #pragma unroll
            for (int h = 0; h < 2; h++) {
                float lpbg = -0.5f * (C0 + bgp[wid][16 * u + 8 * h + g]);
                float lp[16], y[16];
                float mx = -3.4e38f;
                #pragma unroll
                for (int j = 0; j < 8; j++) {
                    int col = 8 * j + 2 * t4;
                    float v0 = fmaf(-0.5f, c[u][j][2*h],   offs_s[col])   + lpbg;
                    float v1 = fmaf(-0.5f, c[u][j][2*h+1], offs_s[col+1]) + lpbg;
                    lp[2*j] = v0; lp[2*j+1] = v1;
                    y[2*j]   = v0 + lpi_s[col];
                    y[2*j+1] = v1 + lpi_s[col+1];
                    mx = fmaxf(mx, fmaxf(y[2*j], y[2*j+1]));
                }
                mx = fmaxf(mx, __shfl_xor_sync(0xffffffffu, mx, 1));
                mx = fmaxf(mx, __shfl_xor_sync(0xffffffffu, mx, 2));

                float mxl = mx * LOG2E_F;
                __half2 e0 = ex2_h2(fmaf(y[0],  LOG2E_F, -mxl), fmaf(y[1],  LOG2E_F, -mxl));
                __half2 e1 = ex2_h2(fmaf(y[2],  LOG2E_F, -mxl), fmaf(y[3],  LOG2E_F, -mxl));
                __half2 e2 = ex2_h2(fmaf(y[4],  LOG2E_F, -mxl), fmaf(y[5],  LOG2E_F, -mxl));
                __half2 e3 = ex2_h2(fmaf(y[6],  LOG2E_F, -mxl), fmaf(y[7],  LOG2E_F, -mxl));
                __half2 e4 = ex2_h2(fmaf(y[8],  LOG2E_F, -mxl), fmaf(y[9],  LOG2E_F, -mxl));
                __half2 e5 = ex2_h2(fmaf(y[10], LOG2E_F, -mxl), fmaf(y[11], LOG2E_F, -mxl));
                __half2 e6 = ex2_h2(fmaf(y[12], LOG2E_F, -mxl), fmaf(y[13], LOG2E_F, -mxl));
                __half2 e7 = ex2_h2(fmaf(y[14], LOG2E_F, -mxl), fmaf(y[15], LOG2E_F, -mxl));
                __half2 s01 = __hadd2(e0, e1), s23 = __hadd2(e2, e3);
                __half2 s45 = __hadd2(e4, e5), s67 = __hadd2(e6, e7);
                float2 f0 = __half22float2(s01), f1 = __half22float2(s23);
                float2 f2 = __half22float2(s45), f3 = __half22float2(s67);
                float se = (f0.x + f0.y) + (f1.x + f1.y)
                         + (f2.x + f2.y) + (f3.x + f3.y);
                se += __shfl_xor_sync(0xffffffffu, se, 1);
                se += __shfl_xor_sync(0xffffffffu, se, 2);
                if (t4 == 0) lsesum += (double)(mx + __logf(se));

                // stage lp (padded stride 68; STS.64 8B-aligned)
                float* srow = buff + (8 * h + g) * 68 + 2 * t4;
                #pragma unroll
                for (int j = 0; j < 8; j++)
                    *(float2*)(srow + 8 * j) = make_float2(lp[2*j], lp[2*j+1]);
            }
            __syncwarp();
            // coalesced copy-out of 16 rows; out+65 is 4B-aligned -> STG.32
            float* ob = out + 65 + (size_t)(row0 + 16 * u) * Kk;
            #pragma unroll
            for (int i = 0; i < 32; i++) {
                int idx = i * 32 + lane;
                ob[idx] = buff[(idx >> 6) * 68 + (idx & 63)];
            }
            __syncwarp();
        }
    }

    // ---- loss reduce + last-CTA finalize (deterministic replay reset) ----
    #pragma unroll
    for (int s = 16; s; s >>= 1)
        lsesum += __shfl_xor_sync(0xffffffffu, lsesum, s);
    if (lane == 0) wsum[wid] = lsesum;
    __syncthreads();
    if (tid == 0) {
        double bsum = 0.0;
        #pragma unroll
        for (int w = 0; w < TPB / 32; w++) bsum += wsum[w];
        atomicAdd(&g_lse, bsum);
        __threadfence();
        unsigned int old = atomicAdd(&g_count, 1u);
        if (old == GRID - 1) {
            __threadfence();
            double total = atomicAdd(&g_lse, 0.0);
            out[0] = (float)((double)kl_s * (double)Nn - total);
            g_lse   = 0.0;
            g_tile  = 0u;
            g_count = 0u;
        }
    }
}

// ---------------------------------------------------------------------------
extern "C" void kernel_launch(void* const* d_in, const int* in_sizes, int n_in,
                              void* d_out, int out_size)
{
    const float* X  = (const float*)d_in[0];
    const float* u  = (const float*)d_in[1];
    const float* pl = (const float*)d_in[2];
    const float* mu = (const float*)d_in[3];
    const float* lv = (const float*)d_in[4];
    const float* pi = (const float*)d_in[5];
    const float* pp = (const float*)d_in[6];
    float* out = (float*)d_out;

    cudaFuncSetAttribute(gmm_kernel,
                         cudaFuncAttributeMaxDynamicSharedMemorySize, SMEM_BYTES);

    gmm_kernel<<<GRID, TPB, SMEM_BYTES>>>(X, u, pl, mu, lv, pi, pp, out);
}